// round 14
// baseline (speedup 1.0000x reference)
#include <cuda_runtime.h>
#include <cuda_fp16.h>
#include <cstdint>

// Problem dims (fixed by the reference)
#define H_DIM   1024
#define I_DIM   2048
#define I2_DIM  4096   // 2*I
#define N_DIM   16
#define P_DIM   33     // 2N+1
#define KCONV   4
#define BATCH   2
#define SEQ     2048
#define M_DIM   4096   // BATCH*SEQ

// Scratch (device globals: allocation-free, graph-capturable)
__device__ __half g_xzh[(size_t)M_DIM * I2_DIM];   // 32 MB (GEMM1 out, fp16)
__device__ __half g_yzh[(size_t)M_DIM * I_DIM];    // 16 MB (ssm out, fp16)
__device__ float  g_xc[(size_t)M_DIM * I_DIM];     // 32 MB (conv+silu out, fp32)
__device__ float  g_proj[(size_t)M_DIM * P_DIM];   // 540 KB
__device__ float  g_Aneg[I_DIM * N_DIM];
__device__ __half g_xrh [(size_t)M_DIM * H_DIM];   // 8 MB (x, fp16)
__device__ __half g_wirh[(size_t)I2_DIM * H_DIM];  // 8 MB (W_in, fp16)
__device__ __half g_worh[(size_t)H_DIM * I_DIM];   // 4 MB (W_out, fp16)

__device__ __forceinline__ uint32_t smem_u32(const void* p) {
    uint32_t a;
    asm("{ .reg .u64 t; cvta.to.shared.u64 t, %1; cvt.u32.u64 %0, t; }" : "=r"(a) : "l"(p));
    return a;
}
__device__ __forceinline__ void cp_async16(uint32_t dst, const void* src) {
    asm volatile("cp.async.cg.shared.global [%0], [%1], 16;" :: "r"(dst), "l"(src));
}
__device__ __forceinline__ uint32_t h2_u32(__half2 h) {
    union { __half2 h; uint32_t u; } cv; cv.h = h; return cv.u;
}
#define LDSM_X4(r0, r1, r2, r3, addr) \
    asm volatile("ldmatrix.sync.aligned.m8n8.x4.shared.b16 {%0,%1,%2,%3}, [%4];" \
                 : "=r"(r0), "=r"(r1), "=r"(r2), "=r"(r3) : "r"(addr))

// ---------------------------------------------------------------------------
// Fused prep: fp32->fp16 for x / W_in / W_out and A = -exp(A_log). One launch.
// ---------------------------------------------------------------------------
#define N8_X   ((M_DIM  * H_DIM) / 8)
#define N8_WI  ((I2_DIM * H_DIM) / 8)
#define N8_WO  ((H_DIM  * I_DIM) / 8)
#define N8_AL  ((I_DIM  * N_DIM) / 8)
#define N8_TOT (N8_X + N8_WI + N8_WO + N8_AL)

__device__ __forceinline__ void cvt8_f16(const float* in, __half* out, int i) {
    float4 a = ((const float4*)in)[2 * i];
    float4 b = ((const float4*)in)[2 * i + 1];
    uint4 u;
    u.x = h2_u32(__floats2half2_rn(a.x, a.y));
    u.y = h2_u32(__floats2half2_rn(a.z, a.w));
    u.z = h2_u32(__floats2half2_rn(b.x, b.y));
    u.w = h2_u32(__floats2half2_rn(b.z, b.w));
    ((uint4*)out)[i] = u;
}

__global__ void prep_kernel(const float* __restrict__ x, const float* __restrict__ W_in,
                            const float* __restrict__ W_out, const float* __restrict__ A_log) {
    int i = blockIdx.x * blockDim.x + threadIdx.x;
    if (i < N8_X) {
        cvt8_f16(x, g_xrh, i);
    } else if (i < N8_X + N8_WI) {
        cvt8_f16(W_in, g_wirh, i - N8_X);
    } else if (i < N8_X + N8_WI + N8_WO) {
        cvt8_f16(W_out, g_worh, i - N8_X - N8_WI);
    } else if (i < N8_TOT) {
        int j = i - (N8_X + N8_WI + N8_WO);
        float4 a = ((const float4*)A_log)[2 * j];
        float4 b = ((const float4*)A_log)[2 * j + 1];
        ((float4*)g_Aneg)[2 * j]     = make_float4(-expf(a.x), -expf(a.y), -expf(a.z), -expf(a.w));
        ((float4*)g_Aneg)[2 * j + 1] = make_float4(-expf(b.x), -expf(b.y), -expf(b.z), -expf(b.w));
    }
}

// ===========================================================================
// FP16 GEMM via mma.sync m16n8k16 (fp32 accum), 3-stage cp.async pipeline,
// ldmatrix.x4 fragment loads. Block tile 128x128x64(k); 128 threads = 4 warps
// (2x2), warp tile 64x64. Templated output type (float or __half).
// ===========================================================================
#define BKH  64
#define PADH 72
#define ROWB (PADH * 2)
#define ABUF32 (128 * (PADH / 2))
#define STAGE_BYTES (ABUF32 * 4)
#define GEMM_SMEM_BYTES (3 * 2 * STAGE_BYTES)   // 110592 B

template<typename OutT>
__global__ __launch_bounds__(128, 2)
void gemm_f16_mma(const __half* __restrict__ A, const __half* __restrict__ B,
                  OutT* __restrict__ C, int M, int N, int K) {
    extern __shared__ uint32_t smw[];
    uint32_t* As = smw;
    uint32_t* Bs = smw + 3 * ABUF32;
    const uint32_t sA = smem_u32(As);
    const uint32_t sB = smem_u32(Bs);

    const int tid  = threadIdx.x;
    const int lane = tid & 31;
    const int wid  = tid >> 5;
    const int wm   = wid >> 1;
    const int wn   = wid & 1;
    const int gid  = lane >> 2;
    const int tig  = lane & 3;
    const int m0   = blockIdx.y * 128;
    const int n0   = blockIdx.x * 128;

    const __half* Ag = A + (size_t)m0 * K;
    const __half* Bg = B + (size_t)n0 * K;

    int lm[8], lk[8];
    uint32_t soff[8];
#pragma unroll
    for (int j = 0; j < 8; j++) {
        int f = tid + 128 * j;
        lm[j] = f >> 3;
        lk[j] = (f & 7) * 8;
        soff[j] = (uint32_t)(lm[j] * ROWB + (f & 7) * 16);
    }

    const uint32_t aLane = (uint32_t)((wm * 64 + (lane & 15)) * ROWB + (lane >> 4) * 16);
    const uint32_t bLane = (uint32_t)((wn * 64 + (lane & 7) + ((lane >> 4) << 3)) * ROWB
                                      + ((lane >> 3) & 1) * 16);

    float acc[4][8][4];
#pragma unroll
    for (int i = 0; i < 4; i++)
#pragma unroll
        for (int j = 0; j < 8; j++)
#pragma unroll
            for (int q = 0; q < 4; q++) acc[i][j][q] = 0.f;

    const int nchunk = K / BKH;

#pragma unroll
    for (int s = 0; s < 2; s++) {
        const int k0 = s * BKH;
        const uint32_t sa = sA + s * STAGE_BYTES;
        const uint32_t sb = sB + s * STAGE_BYTES;
#pragma unroll
        for (int j = 0; j < 8; j++) {
            cp_async16(sa + soff[j], Ag + (size_t)lm[j] * K + k0 + lk[j]);
            cp_async16(sb + soff[j], Bg + (size_t)lm[j] * K + k0 + lk[j]);
        }
        asm volatile("cp.async.commit_group;");
    }

    for (int c = 0; c < nchunk; c++) {
        asm volatile("cp.async.wait_group 1;");
        __syncthreads();

        const int buf = c % 3;
        const uint32_t aBase = sA + buf * STAGE_BYTES + aLane;
        const uint32_t bBase = sB + buf * STAGE_BYTES + bLane;

#pragma unroll
        for (int ks = 0; ks < 4; ks++) {
            const uint32_t kb = ks * 32;
            uint32_t af[4][4];
#pragma unroll
            for (int i = 0; i < 4; i++)
                LDSM_X4(af[i][0], af[i][1], af[i][2], af[i][3],
                        aBase + i * 16 * ROWB + kb);
            uint32_t bf[8][2];
#pragma unroll
            for (int jp = 0; jp < 4; jp++)
                LDSM_X4(bf[2 * jp][0], bf[2 * jp][1], bf[2 * jp + 1][0], bf[2 * jp + 1][1],
                        bBase + jp * 16 * ROWB + kb);
#pragma unroll
            for (int i = 0; i < 4; i++)
#pragma unroll
                for (int j = 0; j < 8; j++) {
                    asm volatile(
                        "mma.sync.aligned.m16n8k16.row.col.f32.f16.f16.f32 "
                        "{%0,%1,%2,%3}, {%4,%5,%6,%7}, {%8,%9}, {%0,%1,%2,%3};"
                        : "+f"(acc[i][j][0]), "+f"(acc[i][j][1]),
                          "+f"(acc[i][j][2]), "+f"(acc[i][j][3])
                        : "r"(af[i][0]), "r"(af[i][1]), "r"(af[i][2]), "r"(af[i][3]),
                          "r"(bf[j][0]), "r"(bf[j][1]));
                }
        }

        const int cn = c + 2;
        if (cn < nchunk) {
            const int k0 = cn * BKH;
            const int nb = cn % 3;
            const uint32_t sa = sA + nb * STAGE_BYTES;
            const uint32_t sb = sB + nb * STAGE_BYTES;
#pragma unroll
            for (int j = 0; j < 8; j++) {
                cp_async16(sa + soff[j], Ag + (size_t)lm[j] * K + k0 + lk[j]);
                cp_async16(sb + soff[j], Bg + (size_t)lm[j] * K + k0 + lk[j]);
            }
        }
        asm volatile("cp.async.commit_group;");
    }

    // Epilogue
#pragma unroll
    for (int i = 0; i < 4; i++) {
        const int r0 = m0 + wm * 64 + i * 16 + gid;
#pragma unroll
        for (int j = 0; j < 8; j++) {
            const int cc = n0 + wn * 64 + j * 8 + 2 * tig;
            if constexpr (sizeof(OutT) == 4) {
                *(float2*)((float*)C + (size_t)r0 * N + cc) =
                    make_float2(acc[i][j][0], acc[i][j][1]);
                *(float2*)((float*)C + (size_t)(r0 + 8) * N + cc) =
                    make_float2(acc[i][j][2], acc[i][j][3]);
            } else {
                *(__half2*)((__half*)C + (size_t)r0 * N + cc) =
                    __floats2half2_rn(acc[i][j][0], acc[i][j][1]);
                *(__half2*)((__half*)C + (size_t)(r0 + 8) * N + cc) =
                    __floats2half2_rn(acc[i][j][2], acc[i][j][3]);
            }
        }
    }
}

// ---------------------------------------------------------------------------
// Middle stage 1: depthwise conv (K=4 causal) + silu. Reads fp16 xz.
// ---------------------------------------------------------------------------
__device__ __forceinline__ float4 ld4h(const __half* p) {
    uint2 v = *(const uint2*)p;
    __half2 h0 = *(__half2*)&v.x;
    __half2 h1 = *(__half2*)&v.y;
    float2 f0 = __half22float2(h0);
    float2 f1 = __half22float2(h1);
    return make_float4(f0.x, f0.y, f1.x, f1.y);
}

__global__ __launch_bounds__(256)
void conv_silu_kernel(const float* __restrict__ conv_w) {
    const int idx = blockIdx.x * blockDim.x + threadIdx.x;
    const int ig  = idx & (I_DIM / 4 - 1);
    const int mg  = idx >> 9;
    const int m0  = mg * 4;
    const int s0  = m0 & (SEQ - 1);
    const int i   = ig * 4;

    const float4 w0 = ((const float4*)conv_w)[i + 0];
    const float4 w1 = ((const float4*)conv_w)[i + 1];
    const float4 w2 = ((const float4*)conv_w)[i + 2];
    const float4 w3 = ((const float4*)conv_w)[i + 3];

    float4 r[7];
#pragma unroll
    for (int t = 0; t < 7; t++) {
        int sp = s0 - 3 + t;
        if (sp >= 0)
            r[t] = ld4h(g_xzh + (size_t)(m0 - 3 + t) * I2_DIM + i);
        else
            r[t] = make_float4(0.f, 0.f, 0.f, 0.f);
    }

#pragma unroll
    for (int o = 0; o < 4; o++) {
        float4 acc;
        acc.x = r[o].x * w0.x + r[o+1].x * w0.y + r[o+2].x * w0.z + r[o+3].x * w0.w;
        acc.y = r[o].y * w1.x + r[o+1].y * w1.y + r[o+2].y * w1.z + r[o+3].y * w1.w;
        acc.z = r[o].z * w2.x + r[o+1].z * w2.y + r[o+2].z * w2.z + r[o+3].z * w2.w;
        acc.w = r[o].w * w3.x + r[o+1].w * w3.y + r[o+2].w * w3.z + r[o+3].w * w3.w;
        acc.x = acc.x / (1.f + __expf(-acc.x));
        acc.y = acc.y / (1.f + __expf(-acc.y));
        acc.z = acc.z / (1.f + __expf(-acc.z));
        acc.w = acc.w / (1.f + __expf(-acc.w));
        ((float4*)g_xc)[(size_t)(m0 + o) * (I_DIM / 4) + ig] = acc;
    }
}

// ---------------------------------------------------------------------------
// Middle stage 2: xproj. 2 rows/warp (best LDS/FMA ratio measured), 256 thr,
// 16 rows/block, W_x chunk 256 in smem (33.8 KB); __launch_bounds__(256,2)
// forces <=128 regs -> 2 blocks/SM (R12 ran 223 regs @ 1 blk/SM).
// ---------------------------------------------------------------------------
#define PROJ_ROWS 16
#define PROJ_KC   256
#define PROJ_SMEM (P_DIM * PROJ_KC * 4)   // 33792 B

__global__ __launch_bounds__(256, 2)
void proj_kernel(const float* __restrict__ W_x) {
    extern __shared__ float wxs[];                 // [33][PROJ_KC]
    const int tid  = threadIdx.x;
    const int lane = tid & 31;
    const int wid  = tid >> 5;
    const int r0   = blockIdx.x * PROJ_ROWS + wid * 2;

    const float* xp0 = g_xc + (size_t)(r0 + 0) * I_DIM;
    const float* xp1 = g_xc + (size_t)(r0 + 1) * I_DIM;

    float acc0[P_DIM], acc1[P_DIM];
#pragma unroll
    for (int p = 0; p < P_DIM; p++) { acc0[p] = 0.f; acc1[p] = 0.f; }

    for (int k0 = 0; k0 < I_DIM; k0 += PROJ_KC) {
        __syncthreads();
        // stage W_x chunk: 33 rows x 64 float4
        for (int f = tid; f < P_DIM * (PROJ_KC / 4); f += 256) {
            int p  = f / (PROJ_KC / 4);
            int kq = f % (PROJ_KC / 4);
            ((float4*)wxs)[f] = ((const float4*)(W_x + (size_t)p * I_DIM + k0))[kq];
        }
        __syncthreads();

#pragma unroll
        for (int it = 0; it < PROJ_KC / 128; it++) {    // 2 iters
            const int kf = it * 32 + lane;              // float4 index in chunk
            float4 x0 = ((const float4*)(xp0 + k0))[kf];
            float4 x1 = ((const float4*)(xp1 + k0))[kf];
#pragma unroll
            for (int p = 0; p < P_DIM; p++) {
                float4 w = ((const float4*)wxs)[p * (PROJ_KC / 4) + kf];
                acc0[p] = fmaf(x0.x, w.x, fmaf(x0.y, w.y, fmaf(x0.z, w.z, fmaf(x0.w, w.w, acc0[p]))));
                acc1[p] = fmaf(x1.x, w.x, fmaf(x1.y, w.y, fmaf(x1.z, w.z, fmaf(x1.w, w.w, acc1[p]))));
            }
        }
    }

#pragma unroll
    for (int p = 0; p < P_DIM; p++) {
        float v0 = acc0[p], v1 = acc1[p];
#pragma unroll
        for (int off = 16; off > 0; off >>= 1) {
            v0 += __shfl_down_sync(0xffffffffu, v0, off);
            v1 += __shfl_down_sync(0xffffffffu, v1, off);
        }
        if (lane == 0) {
            g_proj[(size_t)(r0 + 0) * P_DIM + p] = v0;
            g_proj[(size_t)(r0 + 1) * P_DIM + p] = v1;
        }
    }
}

// ---------------------------------------------------------------------------
// Middle stage 3: ssm + gate. 148 blocks, 27/28 rows each (balanced fill).
// ---------------------------------------------------------------------------
#define SSM_MAXR 28

__global__ __launch_bounds__(256)
void ssm_kernel(const float* __restrict__ D) {
    const int bid  = blockIdx.x;
    const int rows = 27 + (bid < 100 ? 1 : 0);
    const int rb   = bid * 27 + (bid < 100 ? bid : 100);
    const int tid  = threadIdx.x;

    __shared__ float delta_s[SSM_MAXR];
    __shared__ float bc_s[SSM_MAXR][N_DIM];

    if (tid < rows) {
        const float* pr = g_proj + (size_t)(rb + tid) * P_DIM;
        float v = pr[0];
        delta_s[tid] = (v > 20.f) ? v : log1pf(__expf(v));
#pragma unroll
        for (int n = 0; n < N_DIM; n++)
            bc_s[tid][n] = pr[1 + n] * pr[1 + N_DIM + n];
    }
    __syncthreads();

    for (int ii = tid; ii < I_DIM; ii += 256) {
        float a[N_DIM];
        *(float4*)&a[0]  = *(const float4*)(g_Aneg + ii * N_DIM + 0);
        *(float4*)&a[4]  = *(const float4*)(g_Aneg + ii * N_DIM + 4);
        *(float4*)&a[8]  = *(const float4*)(g_Aneg + ii * N_DIM + 8);
        *(float4*)&a[12] = *(const float4*)(g_Aneg + ii * N_DIM + 12);
        const float d = D[ii];

#pragma unroll 4
        for (int mm = 0; mm < rows; mm++) {
            const int m = rb + mm;
            const float delta = delta_s[mm];
            float acc = d;
#pragma unroll
            for (int n = 0; n < N_DIM; n++)
                acc = fmaf(bc_s[mm][n], __expf(delta * a[n]), acc);
            float xcv = g_xc[(size_t)m * I_DIM + ii];
            float zv  = __half2float(g_xzh[(size_t)m * I2_DIM + I_DIM + ii]);
            float gz  = zv / (1.f + __expf(-zv));
            g_yzh[(size_t)m * I_DIM + ii] = __float2half_rn(xcv * acc * gz);
        }
    }
}

// ---------------------------------------------------------------------------
// Launcher
// ---------------------------------------------------------------------------
extern "C" void kernel_launch(void* const* d_in, const int* in_sizes, int n_in,
                              void* d_out, int out_size) {
    const float* x      = (const float*)d_in[0];
    const float* W_in   = (const float*)d_in[1];
    const float* conv_w = (const float*)d_in[2];
    const float* W_x    = (const float*)d_in[3];
    const float* A_log  = (const float*)d_in[4];
    const float* D      = (const float*)d_in[5];
    const float* W_out  = (const float*)d_in[6];
    float* out = (float*)d_out;

    __half *xzh_ptr, *yzh_ptr, *xrh_ptr, *wirh_ptr, *worh_ptr;
    cudaGetSymbolAddress((void**)&xzh_ptr,  g_xzh);
    cudaGetSymbolAddress((void**)&yzh_ptr,  g_yzh);
    cudaGetSymbolAddress((void**)&xrh_ptr,  g_xrh);
    cudaGetSymbolAddress((void**)&wirh_ptr, g_wirh);
    cudaGetSymbolAddress((void**)&worh_ptr, g_worh);

    cudaFuncSetAttribute(gemm_f16_mma<__half>,
                         cudaFuncAttributeMaxDynamicSharedMemorySize, GEMM_SMEM_BYTES);
    cudaFuncSetAttribute(gemm_f16_mma<float>,
                         cudaFuncAttributeMaxDynamicSharedMemorySize, GEMM_SMEM_BYTES);
    cudaFuncSetAttribute(proj_kernel,
                         cudaFuncAttributeMaxDynamicSharedMemorySize, PROJ_SMEM);

    // 0) fused prep: fp16 conversions + A = -exp(A_log)
    prep_kernel<<<(N8_TOT + 255) / 256, 256>>>(x, W_in, W_out, A_log);

    // 1) xz = x @ W_in^T : M=4096, N=4096, K=1024 (fp16 out)
    {
        dim3 grid(I2_DIM / 128, M_DIM / 128);
        gemm_f16_mma<__half><<<grid, 128, GEMM_SMEM_BYTES>>>(xrh_ptr, wirh_ptr, xzh_ptr,
                                                             M_DIM, I2_DIM, H_DIM);
    }

    // 2) middle
    conv_silu_kernel<<<(M_DIM / 4) * (I_DIM / 4) / 256, 256>>>(conv_w);
    proj_kernel<<<M_DIM / PROJ_ROWS, 256, PROJ_SMEM>>>(W_x);
    ssm_kernel<<<148, 256>>>(D);

    // 3) out = yz @ W_out^T : M=4096, N=1024, K=2048 (fp32 out)
    {
        dim3 grid(H_DIM / 128, M_DIM / 128);
        gemm_f16_mma<float><<<grid, 128, GEMM_SMEM_BYTES>>>(yzh_ptr, worh_ptr, out,
                                                            M_DIM, H_DIM, I_DIM);
    }
}

// round 15
// speedup vs baseline: 1.5031x; 1.5031x over previous
#include <cuda_runtime.h>
#include <cuda_fp16.h>
#include <cstdint>

// Problem dims (fixed by the reference)
#define H_DIM   1024
#define I_DIM   2048
#define I2_DIM  4096   // 2*I
#define N_DIM   16
#define P_DIM   33     // 2N+1
#define KCONV   4
#define BATCH   2
#define SEQ     2048
#define M_DIM   4096   // BATCH*SEQ

// Scratch (device globals: allocation-free, graph-capturable)
__device__ __half g_xzh[(size_t)M_DIM * I2_DIM];   // 32 MB (GEMM1 out, fp16)
__device__ __half g_yzh[(size_t)M_DIM * I_DIM];    // 16 MB (ssm out, fp16)
__device__ __half g_xch[(size_t)M_DIM * I_DIM];    // 16 MB (conv+silu out, fp16)
__device__ float  g_proj[(size_t)M_DIM * P_DIM];   // 540 KB
__device__ float  g_Aneg[I_DIM * N_DIM];
__device__ __half g_xrh [(size_t)M_DIM * H_DIM];   // 8 MB (x, fp16)
__device__ __half g_wirh[(size_t)I2_DIM * H_DIM];  // 8 MB (W_in, fp16)
__device__ __half g_worh[(size_t)H_DIM * I_DIM];   // 4 MB (W_out, fp16)

__device__ __forceinline__ uint32_t smem_u32(const void* p) {
    uint32_t a;
    asm("{ .reg .u64 t; cvta.to.shared.u64 t, %1; cvt.u32.u64 %0, t; }" : "=r"(a) : "l"(p));
    return a;
}
__device__ __forceinline__ void cp_async16(uint32_t dst, const void* src) {
    asm volatile("cp.async.cg.shared.global [%0], [%1], 16;" :: "r"(dst), "l"(src));
}
__device__ __forceinline__ uint32_t h2_u32(__half2 h) {
    union { __half2 h; uint32_t u; } cv; cv.h = h; return cv.u;
}
#define LDSM_X4(r0, r1, r2, r3, addr) \
    asm volatile("ldmatrix.sync.aligned.m8n8.x4.shared.b16 {%0,%1,%2,%3}, [%4];" \
                 : "=r"(r0), "=r"(r1), "=r"(r2), "=r"(r3) : "r"(addr))

// ---------------------------------------------------------------------------
// Fused prep: fp32->fp16 for x / W_in / W_out and A = -exp(A_log). One launch.
// ---------------------------------------------------------------------------
#define N8_X   ((M_DIM  * H_DIM) / 8)
#define N8_WI  ((I2_DIM * H_DIM) / 8)
#define N8_WO  ((H_DIM  * I_DIM) / 8)
#define N8_AL  ((I_DIM  * N_DIM) / 8)
#define N8_TOT (N8_X + N8_WI + N8_WO + N8_AL)

__device__ __forceinline__ void cvt8_f16(const float* in, __half* out, int i) {
    float4 a = ((const float4*)in)[2 * i];
    float4 b = ((const float4*)in)[2 * i + 1];
    uint4 u;
    u.x = h2_u32(__floats2half2_rn(a.x, a.y));
    u.y = h2_u32(__floats2half2_rn(a.z, a.w));
    u.z = h2_u32(__floats2half2_rn(b.x, b.y));
    u.w = h2_u32(__floats2half2_rn(b.z, b.w));
    ((uint4*)out)[i] = u;
}

__global__ void prep_kernel(const float* __restrict__ x, const float* __restrict__ W_in,
                            const float* __restrict__ W_out, const float* __restrict__ A_log) {
    int i = blockIdx.x * blockDim.x + threadIdx.x;
    if (i < N8_X) {
        cvt8_f16(x, g_xrh, i);
    } else if (i < N8_X + N8_WI) {
        cvt8_f16(W_in, g_wirh, i - N8_X);
    } else if (i < N8_X + N8_WI + N8_WO) {
        cvt8_f16(W_out, g_worh, i - N8_X - N8_WI);
    } else if (i < N8_TOT) {
        int j = i - (N8_X + N8_WI + N8_WO);
        float4 a = ((const float4*)A_log)[2 * j];
        float4 b = ((const float4*)A_log)[2 * j + 1];
        ((float4*)g_Aneg)[2 * j]     = make_float4(-expf(a.x), -expf(a.y), -expf(a.z), -expf(a.w));
        ((float4*)g_Aneg)[2 * j + 1] = make_float4(-expf(b.x), -expf(b.y), -expf(b.z), -expf(b.w));
    }
}

// ===========================================================================
// FP16 GEMM via mma.sync m16n8k16 (fp32 accum), 3-stage cp.async pipeline,
// ldmatrix.x4 fragment loads. Block tile 128x128x64(k); 128 threads = 4 warps
// (2x2), warp tile 64x64. Templated output type (float or __half).
// ===========================================================================
#define BKH  64
#define PADH 72
#define ROWB (PADH * 2)
#define ABUF32 (128 * (PADH / 2))
#define STAGE_BYTES (ABUF32 * 4)
#define GEMM_SMEM_BYTES (3 * 2 * STAGE_BYTES)   // 110592 B

template<typename OutT>
__global__ __launch_bounds__(128, 2)
void gemm_f16_mma(const __half* __restrict__ A, const __half* __restrict__ B,
                  OutT* __restrict__ C, int M, int N, int K) {
    extern __shared__ uint32_t smw[];
    uint32_t* As = smw;
    uint32_t* Bs = smw + 3 * ABUF32;
    const uint32_t sA = smem_u32(As);
    const uint32_t sB = smem_u32(Bs);

    const int tid  = threadIdx.x;
    const int lane = tid & 31;
    const int wid  = tid >> 5;
    const int wm   = wid >> 1;
    const int wn   = wid & 1;
    const int gid  = lane >> 2;
    const int tig  = lane & 3;
    const int m0   = blockIdx.y * 128;
    const int n0   = blockIdx.x * 128;

    const __half* Ag = A + (size_t)m0 * K;
    const __half* Bg = B + (size_t)n0 * K;

    int lm[8], lk[8];
    uint32_t soff[8];
#pragma unroll
    for (int j = 0; j < 8; j++) {
        int f = tid + 128 * j;
        lm[j] = f >> 3;
        lk[j] = (f & 7) * 8;
        soff[j] = (uint32_t)(lm[j] * ROWB + (f & 7) * 16);
    }

    const uint32_t aLane = (uint32_t)((wm * 64 + (lane & 15)) * ROWB + (lane >> 4) * 16);
    const uint32_t bLane = (uint32_t)((wn * 64 + (lane & 7) + ((lane >> 4) << 3)) * ROWB
                                      + ((lane >> 3) & 1) * 16);

    float acc[4][8][4];
#pragma unroll
    for (int i = 0; i < 4; i++)
#pragma unroll
        for (int j = 0; j < 8; j++)
#pragma unroll
            for (int q = 0; q < 4; q++) acc[i][j][q] = 0.f;

    const int nchunk = K / BKH;

#pragma unroll
    for (int s = 0; s < 2; s++) {
        const int k0 = s * BKH;
        const uint32_t sa = sA + s * STAGE_BYTES;
        const uint32_t sb = sB + s * STAGE_BYTES;
#pragma unroll
        for (int j = 0; j < 8; j++) {
            cp_async16(sa + soff[j], Ag + (size_t)lm[j] * K + k0 + lk[j]);
            cp_async16(sb + soff[j], Bg + (size_t)lm[j] * K + k0 + lk[j]);
        }
        asm volatile("cp.async.commit_group;");
    }

    for (int c = 0; c < nchunk; c++) {
        asm volatile("cp.async.wait_group 1;");
        __syncthreads();

        const int buf = c % 3;
        const uint32_t aBase = sA + buf * STAGE_BYTES + aLane;
        const uint32_t bBase = sB + buf * STAGE_BYTES + bLane;

#pragma unroll
        for (int ks = 0; ks < 4; ks++) {
            const uint32_t kb = ks * 32;
            uint32_t af[4][4];
#pragma unroll
            for (int i = 0; i < 4; i++)
                LDSM_X4(af[i][0], af[i][1], af[i][2], af[i][3],
                        aBase + i * 16 * ROWB + kb);
            uint32_t bf[8][2];
#pragma unroll
            for (int jp = 0; jp < 4; jp++)
                LDSM_X4(bf[2 * jp][0], bf[2 * jp][1], bf[2 * jp + 1][0], bf[2 * jp + 1][1],
                        bBase + jp * 16 * ROWB + kb);
#pragma unroll
            for (int i = 0; i < 4; i++)
#pragma unroll
                for (int j = 0; j < 8; j++) {
                    asm volatile(
                        "mma.sync.aligned.m16n8k16.row.col.f32.f16.f16.f32 "
                        "{%0,%1,%2,%3}, {%4,%5,%6,%7}, {%8,%9}, {%0,%1,%2,%3};"
                        : "+f"(acc[i][j][0]), "+f"(acc[i][j][1]),
                          "+f"(acc[i][j][2]), "+f"(acc[i][j][3])
                        : "r"(af[i][0]), "r"(af[i][1]), "r"(af[i][2]), "r"(af[i][3]),
                          "r"(bf[j][0]), "r"(bf[j][1]));
                }
        }

        const int cn = c + 2;
        if (cn < nchunk) {
            const int k0 = cn * BKH;
            const int nb = cn % 3;
            const uint32_t sa = sA + nb * STAGE_BYTES;
            const uint32_t sb = sB + nb * STAGE_BYTES;
#pragma unroll
            for (int j = 0; j < 8; j++) {
                cp_async16(sa + soff[j], Ag + (size_t)lm[j] * K + k0 + lk[j]);
                cp_async16(sb + soff[j], Bg + (size_t)lm[j] * K + k0 + lk[j]);
            }
        }
        asm volatile("cp.async.commit_group;");
    }

    // Epilogue
#pragma unroll
    for (int i = 0; i < 4; i++) {
        const int r0 = m0 + wm * 64 + i * 16 + gid;
#pragma unroll
        for (int j = 0; j < 8; j++) {
            const int cc = n0 + wn * 64 + j * 8 + 2 * tig;
            if constexpr (sizeof(OutT) == 4) {
                *(float2*)((float*)C + (size_t)r0 * N + cc) =
                    make_float2(acc[i][j][0], acc[i][j][1]);
                *(float2*)((float*)C + (size_t)(r0 + 8) * N + cc) =
                    make_float2(acc[i][j][2], acc[i][j][3]);
            } else {
                *(__half2*)((__half*)C + (size_t)r0 * N + cc) =
                    __floats2half2_rn(acc[i][j][0], acc[i][j][1]);
                *(__half2*)((__half*)C + (size_t)(r0 + 8) * N + cc) =
                    __floats2half2_rn(acc[i][j][2], acc[i][j][3]);
            }
        }
    }
}

// ---------------------------------------------------------------------------
// Middle stage 1: depthwise conv (K=4 causal) + silu. fp16 in, fp16 out.
// ---------------------------------------------------------------------------
__device__ __forceinline__ float4 ld4h(const __half* p) {
    uint2 v = *(const uint2*)p;
    __half2 h0 = *(__half2*)&v.x;
    __half2 h1 = *(__half2*)&v.y;
    float2 f0 = __half22float2(h0);
    float2 f1 = __half22float2(h1);
    return make_float4(f0.x, f0.y, f1.x, f1.y);
}

__global__ __launch_bounds__(256)
void conv_silu_kernel(const float* __restrict__ conv_w) {
    const int idx = blockIdx.x * blockDim.x + threadIdx.x;
    const int ig  = idx & (I_DIM / 4 - 1);
    const int mg  = idx >> 9;
    const int m0  = mg * 4;
    const int s0  = m0 & (SEQ - 1);
    const int i   = ig * 4;

    const float4 w0 = ((const float4*)conv_w)[i + 0];
    const float4 w1 = ((const float4*)conv_w)[i + 1];
    const float4 w2 = ((const float4*)conv_w)[i + 2];
    const float4 w3 = ((const float4*)conv_w)[i + 3];

    float4 r[7];
#pragma unroll
    for (int t = 0; t < 7; t++) {
        int sp = s0 - 3 + t;
        if (sp >= 0)
            r[t] = ld4h(g_xzh + (size_t)(m0 - 3 + t) * I2_DIM + i);
        else
            r[t] = make_float4(0.f, 0.f, 0.f, 0.f);
    }

#pragma unroll
    for (int o = 0; o < 4; o++) {
        float4 acc;
        acc.x = r[o].x * w0.x + r[o+1].x * w0.y + r[o+2].x * w0.z + r[o+3].x * w0.w;
        acc.y = r[o].y * w1.x + r[o+1].y * w1.y + r[o+2].y * w1.z + r[o+3].y * w1.w;
        acc.z = r[o].z * w2.x + r[o+1].z * w2.y + r[o+2].z * w2.z + r[o+3].z * w2.w;
        acc.w = r[o].w * w3.x + r[o+1].w * w3.y + r[o+2].w * w3.z + r[o+3].w * w3.w;
        acc.x = acc.x / (1.f + __expf(-acc.x));
        acc.y = acc.y / (1.f + __expf(-acc.y));
        acc.z = acc.z / (1.f + __expf(-acc.z));
        acc.w = acc.w / (1.f + __expf(-acc.w));
        uint2 st;
        st.x = h2_u32(__floats2half2_rn(acc.x, acc.y));
        st.y = h2_u32(__floats2half2_rn(acc.z, acc.w));
        *(uint2*)(g_xch + (size_t)(m0 + o) * I_DIM + i) = st;
    }
}

// ---------------------------------------------------------------------------
// Middle stage 2: xproj. 2 rows/warp, 256 thr, 16 rows/block, W_x chunk 256
// staged in smem (33.8 KB). Reads fp16 xc. (R12 config — measured fastest.)
// ---------------------------------------------------------------------------
#define PROJ_ROWS 16
#define PROJ_KC   256
#define PROJ_SMEM (P_DIM * PROJ_KC * 4)   // 33792 B

__global__ __launch_bounds__(256)
void proj_kernel(const float* __restrict__ W_x) {
    extern __shared__ float wxs[];                 // [33][PROJ_KC]
    const int tid  = threadIdx.x;
    const int lane = tid & 31;
    const int wid  = tid >> 5;
    const int r0   = blockIdx.x * PROJ_ROWS + wid * 2;

    const __half* xp0 = g_xch + (size_t)(r0 + 0) * I_DIM;
    const __half* xp1 = g_xch + (size_t)(r0 + 1) * I_DIM;

    float acc0[P_DIM], acc1[P_DIM];
#pragma unroll
    for (int p = 0; p < P_DIM; p++) { acc0[p] = 0.f; acc1[p] = 0.f; }

    for (int k0 = 0; k0 < I_DIM; k0 += PROJ_KC) {
        __syncthreads();
        // stage W_x chunk: 33 rows x 64 float4
        for (int f = tid; f < P_DIM * (PROJ_KC / 4); f += 256) {
            int p  = f / (PROJ_KC / 4);
            int kq = f % (PROJ_KC / 4);
            ((float4*)wxs)[f] = ((const float4*)(W_x + (size_t)p * I_DIM + k0))[kq];
        }
        __syncthreads();

#pragma unroll
        for (int it = 0; it < PROJ_KC / 128; it++) {    // 2 iters
            const int kf = it * 32 + lane;              // float4-equivalent index
            float4 x0 = ld4h(xp0 + k0 + kf * 4);
            float4 x1 = ld4h(xp1 + k0 + kf * 4);
#pragma unroll
            for (int p = 0; p < P_DIM; p++) {
                float4 w = ((const float4*)wxs)[p * (PROJ_KC / 4) + kf];
                acc0[p] = fmaf(x0.x, w.x, fmaf(x0.y, w.y, fmaf(x0.z, w.z, fmaf(x0.w, w.w, acc0[p]))));
                acc1[p] = fmaf(x1.x, w.x, fmaf(x1.y, w.y, fmaf(x1.z, w.z, fmaf(x1.w, w.w, acc1[p]))));
            }
        }
    }

#pragma unroll
    for (int p = 0; p < P_DIM; p++) {
        float v0 = acc0[p], v1 = acc1[p];
#pragma unroll
        for (int off = 16; off > 0; off >>= 1) {
            v0 += __shfl_down_sync(0xffffffffu, v0, off);
            v1 += __shfl_down_sync(0xffffffffu, v1, off);
        }
        if (lane == 0) {
            g_proj[(size_t)(r0 + 0) * P_DIM + p] = v0;
            g_proj[(size_t)(r0 + 1) * P_DIM + p] = v1;
        }
    }
}

// ---------------------------------------------------------------------------
// Middle stage 3: ssm + gate. 148 blocks, 27/28 rows each (balanced fill).
// Reads fp16 xc/z; writes fp16 yz.
// ---------------------------------------------------------------------------
#define SSM_MAXR 28

__global__ __launch_bounds__(256)
void ssm_kernel(const float* __restrict__ D) {
    const int bid  = blockIdx.x;
    const int rows = 27 + (bid < 100 ? 1 : 0);
    const int rb   = bid * 27 + (bid < 100 ? bid : 100);
    const int tid  = threadIdx.x;

    __shared__ float delta_s[SSM_MAXR];
    __shared__ float bc_s[SSM_MAXR][N_DIM];

    if (tid < rows) {
        const float* pr = g_proj + (size_t)(rb + tid) * P_DIM;
        float v = pr[0];
        delta_s[tid] = (v > 20.f) ? v : log1pf(__expf(v));
#pragma unroll
        for (int n = 0; n < N_DIM; n++)
            bc_s[tid][n] = pr[1 + n] * pr[1 + N_DIM + n];
    }
    __syncthreads();

    for (int ii = tid; ii < I_DIM; ii += 256) {
        float a[N_DIM];
        *(float4*)&a[0]  = *(const float4*)(g_Aneg + ii * N_DIM + 0);
        *(float4*)&a[4]  = *(const float4*)(g_Aneg + ii * N_DIM + 4);
        *(float4*)&a[8]  = *(const float4*)(g_Aneg + ii * N_DIM + 8);
        *(float4*)&a[12] = *(const float4*)(g_Aneg + ii * N_DIM + 12);
        const float d = D[ii];

#pragma unroll 4
        for (int mm = 0; mm < rows; mm++) {
            const int m = rb + mm;
            const float delta = delta_s[mm];
            float acc = d;
#pragma unroll
            for (int n = 0; n < N_DIM; n++)
                acc = fmaf(bc_s[mm][n], __expf(delta * a[n]), acc);
            float xcv = __half2float(g_xch[(size_t)m * I_DIM + ii]);
            float zv  = __half2float(g_xzh[(size_t)m * I2_DIM + I_DIM + ii]);
            float gz  = zv / (1.f + __expf(-zv));
            g_yzh[(size_t)m * I_DIM + ii] = __float2half_rn(xcv * acc * gz);
        }
    }
}

// ---------------------------------------------------------------------------
// Launcher
// ---------------------------------------------------------------------------
extern "C" void kernel_launch(void* const* d_in, const int* in_sizes, int n_in,
                              void* d_out, int out_size) {
    const float* x      = (const float*)d_in[0];
    const float* W_in   = (const float*)d_in[1];
    const float* conv_w = (const float*)d_in[2];
    const float* W_x    = (const float*)d_in[3];
    const float* A_log  = (const float*)d_in[4];
    const float* D      = (const float*)d_in[5];
    const float* W_out  = (const float*)d_in[6];
    float* out = (float*)d_out;

    __half *xzh_ptr, *yzh_ptr, *xrh_ptr, *wirh_ptr, *worh_ptr;
    cudaGetSymbolAddress((void**)&xzh_ptr,  g_xzh);
    cudaGetSymbolAddress((void**)&yzh_ptr,  g_yzh);
    cudaGetSymbolAddress((void**)&xrh_ptr,  g_xrh);
    cudaGetSymbolAddress((void**)&wirh_ptr, g_wirh);
    cudaGetSymbolAddress((void**)&worh_ptr, g_worh);

    cudaFuncSetAttribute(gemm_f16_mma<__half>,
                         cudaFuncAttributeMaxDynamicSharedMemorySize, GEMM_SMEM_BYTES);
    cudaFuncSetAttribute(gemm_f16_mma<float>,
                         cudaFuncAttributeMaxDynamicSharedMemorySize, GEMM_SMEM_BYTES);
    cudaFuncSetAttribute(proj_kernel,
                         cudaFuncAttributeMaxDynamicSharedMemorySize, PROJ_SMEM);

    // 0) fused prep: fp16 conversions + A = -exp(A_log)
    prep_kernel<<<(N8_TOT + 255) / 256, 256>>>(x, W_in, W_out, A_log);

    // 1) xz = x @ W_in^T : M=4096, N=4096, K=1024 (fp16 out)
    {
        dim3 grid(I2_DIM / 128, M_DIM / 128);
        gemm_f16_mma<__half><<<grid, 128, GEMM_SMEM_BYTES>>>(xrh_ptr, wirh_ptr, xzh_ptr,
                                                             M_DIM, I2_DIM, H_DIM);
    }

    // 2) middle
    conv_silu_kernel<<<(M_DIM / 4) * (I_DIM / 4) / 256, 256>>>(conv_w);
    proj_kernel<<<M_DIM / PROJ_ROWS, 256, PROJ_SMEM>>>(W_x);
    ssm_kernel<<<148, 256>>>(D);

    // 3) out = yz @ W_out^T : M=4096, N=1024, K=2048 (fp32 out)
    {
        dim3 grid(H_DIM / 128, M_DIM / 128);
        gemm_f16_mma<float><<<grid, 128, GEMM_SMEM_BYTES>>>(yzh_ptr, worh_ptr, out,
                                                            M_DIM, H_DIM, I_DIM);
    }
}

// round 16
// speedup vs baseline: 1.5269x; 1.0158x over previous
#include <cuda_runtime.h>
#include <cuda_fp16.h>
#include <cstdint>

// Problem dims (fixed by the reference)
#define H_DIM   1024
#define I_DIM   2048
#define I2_DIM  4096   // 2*I
#define N_DIM   16
#define P_DIM   33     // 2N+1
#define KCONV   4
#define BATCH   2
#define SEQ     2048
#define M_DIM   4096   // BATCH*SEQ

// Scratch (device globals: allocation-free, graph-capturable)
__device__ __half g_xzh[(size_t)M_DIM * I2_DIM];   // 32 MB (GEMM1 out, fp16)
__device__ __half g_yzh[(size_t)M_DIM * I_DIM];    // 16 MB (ssm out, fp16)
__device__ __half g_xch[(size_t)M_DIM * I_DIM];    // 16 MB (conv+silu out, fp16)
__device__ float  g_proj[(size_t)M_DIM * P_DIM];   // 540 KB
__device__ float  g_Aneg[I_DIM * N_DIM];
__device__ __half g_xrh [(size_t)M_DIM * H_DIM];   // 8 MB (x, fp16)
__device__ __half g_wirh[(size_t)I2_DIM * H_DIM];  // 8 MB (W_in, fp16)
__device__ __half g_worh[(size_t)H_DIM * I_DIM];   // 4 MB (W_out, fp16)

__device__ __forceinline__ uint32_t smem_u32(const void* p) {
    uint32_t a;
    asm("{ .reg .u64 t; cvta.to.shared.u64 t, %1; cvt.u32.u64 %0, t; }" : "=r"(a) : "l"(p));
    return a;
}
__device__ __forceinline__ void cp_async16(uint32_t dst, const void* src) {
    asm volatile("cp.async.cg.shared.global [%0], [%1], 16;" :: "r"(dst), "l"(src));
}
__device__ __forceinline__ uint32_t h2_u32(__half2 h) {
    union { __half2 h; uint32_t u; } cv; cv.h = h; return cv.u;
}
#define LDSM_X4(r0, r1, r2, r3, addr) \
    asm volatile("ldmatrix.sync.aligned.m8n8.x4.shared.b16 {%0,%1,%2,%3}, [%4];" \
                 : "=r"(r0), "=r"(r1), "=r"(r2), "=r"(r3) : "r"(addr))

// ---------------------------------------------------------------------------
// Fused prep: fp32->fp16 for x / W_in / W_out and A = -exp(A_log). One launch.
// ---------------------------------------------------------------------------
#define N8_X   ((M_DIM  * H_DIM) / 8)
#define N8_WI  ((I2_DIM * H_DIM) / 8)
#define N8_WO  ((H_DIM  * I_DIM) / 8)
#define N8_AL  ((I_DIM  * N_DIM) / 8)
#define N8_TOT (N8_X + N8_WI + N8_WO + N8_AL)

__device__ __forceinline__ void cvt8_f16(const float* in, __half* out, int i) {
    float4 a = ((const float4*)in)[2 * i];
    float4 b = ((const float4*)in)[2 * i + 1];
    uint4 u;
    u.x = h2_u32(__floats2half2_rn(a.x, a.y));
    u.y = h2_u32(__floats2half2_rn(a.z, a.w));
    u.z = h2_u32(__floats2half2_rn(b.x, b.y));
    u.w = h2_u32(__floats2half2_rn(b.z, b.w));
    ((uint4*)out)[i] = u;
}

__global__ void prep_kernel(const float* __restrict__ x, const float* __restrict__ W_in,
                            const float* __restrict__ W_out, const float* __restrict__ A_log) {
    int i = blockIdx.x * blockDim.x + threadIdx.x;
    if (i < N8_X) {
        cvt8_f16(x, g_xrh, i);
    } else if (i < N8_X + N8_WI) {
        cvt8_f16(W_in, g_wirh, i - N8_X);
    } else if (i < N8_X + N8_WI + N8_WO) {
        cvt8_f16(W_out, g_worh, i - N8_X - N8_WI);
    } else if (i < N8_TOT) {
        int j = i - (N8_X + N8_WI + N8_WO);
        float4 a = ((const float4*)A_log)[2 * j];
        float4 b = ((const float4*)A_log)[2 * j + 1];
        ((float4*)g_Aneg)[2 * j]     = make_float4(-expf(a.x), -expf(a.y), -expf(a.z), -expf(a.w));
        ((float4*)g_Aneg)[2 * j + 1] = make_float4(-expf(b.x), -expf(b.y), -expf(b.z), -expf(b.w));
    }
}

// ===========================================================================
// FP16 GEMM via mma.sync m16n8k16 (fp32 accum), 3-stage cp.async pipeline,
// ldmatrix.x4 fragment loads, PERSISTENT grid-stride over tiles (kills wave
// quantization: GEMM1 = 1024 tiles over 296 CTAs). Block tile 128x128x64(k);
// 128 threads = 4 warps (2x2), warp tile 64x64.
// ===========================================================================
#define BKH  64
#define PADH 72
#define ROWB (PADH * 2)
#define ABUF32 (128 * (PADH / 2))
#define STAGE_BYTES (ABUF32 * 4)
#define GEMM_SMEM_BYTES (3 * 2 * STAGE_BYTES)   // 110592 B
#define GEMM_GRID 296                            // 2 CTAs/SM x 148 SMs

template<typename OutT>
__global__ __launch_bounds__(128, 2)
void gemm_f16_mma(const __half* __restrict__ A, const __half* __restrict__ B,
                  OutT* __restrict__ C, int M, int N, int K) {
    extern __shared__ uint32_t smw[];
    uint32_t* As = smw;
    uint32_t* Bs = smw + 3 * ABUF32;
    const uint32_t sA = smem_u32(As);
    const uint32_t sB = smem_u32(Bs);

    const int tid  = threadIdx.x;
    const int lane = tid & 31;
    const int wid  = tid >> 5;
    const int wm   = wid >> 1;
    const int wn   = wid & 1;
    const int gid  = lane >> 2;
    const int tig  = lane & 3;

    const int ntn = N >> 7;                   // tiles along N
    const int ntiles = (M >> 7) * ntn;

    // Per-thread copy coords (tile-relative)
    int lm[8], lk[8];
    uint32_t soff[8];
#pragma unroll
    for (int j = 0; j < 8; j++) {
        int f = tid + 128 * j;
        lm[j] = f >> 3;
        lk[j] = (f & 7) * 8;
        soff[j] = (uint32_t)(lm[j] * ROWB + (f & 7) * 16);
    }

    const uint32_t aLane = (uint32_t)((wm * 64 + (lane & 15)) * ROWB + (lane >> 4) * 16);
    const uint32_t bLane = (uint32_t)((wn * 64 + (lane & 7) + ((lane >> 4) << 3)) * ROWB
                                      + ((lane >> 3) & 1) * 16);

    const int nchunk = K / BKH;

    for (int t = blockIdx.x; t < ntiles; t += GEMM_GRID) {
        const int m0 = (t / ntn) * 128;
        const int n0 = (t % ntn) * 128;
        const __half* Ag = A + (size_t)m0 * K;
        const __half* Bg = B + (size_t)n0 * K;

        float acc[4][8][4];
#pragma unroll
        for (int i = 0; i < 4; i++)
#pragma unroll
            for (int j = 0; j < 8; j++)
#pragma unroll
                for (int q = 0; q < 4; q++) acc[i][j][q] = 0.f;

#pragma unroll
        for (int s = 0; s < 2; s++) {
            const int k0 = s * BKH;
            const uint32_t sa = sA + s * STAGE_BYTES;
            const uint32_t sb = sB + s * STAGE_BYTES;
#pragma unroll
            for (int j = 0; j < 8; j++) {
                cp_async16(sa + soff[j], Ag + (size_t)lm[j] * K + k0 + lk[j]);
                cp_async16(sb + soff[j], Bg + (size_t)lm[j] * K + k0 + lk[j]);
            }
            asm volatile("cp.async.commit_group;");
        }

        for (int c = 0; c < nchunk; c++) {
            asm volatile("cp.async.wait_group 1;");
            __syncthreads();

            const int buf = c % 3;
            const uint32_t aBase = sA + buf * STAGE_BYTES + aLane;
            const uint32_t bBase = sB + buf * STAGE_BYTES + bLane;

#pragma unroll
            for (int ks = 0; ks < 4; ks++) {
                const uint32_t kb = ks * 32;
                uint32_t af[4][4];
#pragma unroll
                for (int i = 0; i < 4; i++)
                    LDSM_X4(af[i][0], af[i][1], af[i][2], af[i][3],
                            aBase + i * 16 * ROWB + kb);
                uint32_t bf[8][2];
#pragma unroll
                for (int jp = 0; jp < 4; jp++)
                    LDSM_X4(bf[2 * jp][0], bf[2 * jp][1], bf[2 * jp + 1][0], bf[2 * jp + 1][1],
                            bBase + jp * 16 * ROWB + kb);
#pragma unroll
                for (int i = 0; i < 4; i++)
#pragma unroll
                    for (int j = 0; j < 8; j++) {
                        asm volatile(
                            "mma.sync.aligned.m16n8k16.row.col.f32.f16.f16.f32 "
                            "{%0,%1,%2,%3}, {%4,%5,%6,%7}, {%8,%9}, {%0,%1,%2,%3};"
                            : "+f"(acc[i][j][0]), "+f"(acc[i][j][1]),
                              "+f"(acc[i][j][2]), "+f"(acc[i][j][3])
                            : "r"(af[i][0]), "r"(af[i][1]), "r"(af[i][2]), "r"(af[i][3]),
                              "r"(bf[j][0]), "r"(bf[j][1]));
                    }
            }

            const int cn = c + 2;
            if (cn < nchunk) {
                const int k0 = cn * BKH;
                const int nb = cn % 3;
                const uint32_t sa = sA + nb * STAGE_BYTES;
                const uint32_t sb = sB + nb * STAGE_BYTES;
#pragma unroll
                for (int j = 0; j < 8; j++) {
                    cp_async16(sa + soff[j], Ag + (size_t)lm[j] * K + k0 + lk[j]);
                    cp_async16(sb + soff[j], Bg + (size_t)lm[j] * K + k0 + lk[j]);
                }
            }
            asm volatile("cp.async.commit_group;");
        }

        // Drain pending copies before next tile reuses smem.
        asm volatile("cp.async.wait_group 0;");
        __syncthreads();

        // Epilogue
#pragma unroll
        for (int i = 0; i < 4; i++) {
            const int r0 = m0 + wm * 64 + i * 16 + gid;
#pragma unroll
            for (int j = 0; j < 8; j++) {
                const int cc = n0 + wn * 64 + j * 8 + 2 * tig;
                if constexpr (sizeof(OutT) == 4) {
                    *(float2*)((float*)C + (size_t)r0 * N + cc) =
                        make_float2(acc[i][j][0], acc[i][j][1]);
                    *(float2*)((float*)C + (size_t)(r0 + 8) * N + cc) =
                        make_float2(acc[i][j][2], acc[i][j][3]);
                } else {
                    *(__half2*)((__half*)C + (size_t)r0 * N + cc) =
                        __floats2half2_rn(acc[i][j][0], acc[i][j][1]);
                    *(__half2*)((__half*)C + (size_t)(r0 + 8) * N + cc) =
                        __floats2half2_rn(acc[i][j][2], acc[i][j][3]);
                }
            }
        }
    }
}

// ---------------------------------------------------------------------------
// Middle stage 1: depthwise conv (K=4 causal) + silu. fp16 in, fp16 out.
// ---------------------------------------------------------------------------
__device__ __forceinline__ float4 ld4h(const __half* p) {
    uint2 v = *(const uint2*)p;
    __half2 h0 = *(__half2*)&v.x;
    __half2 h1 = *(__half2*)&v.y;
    float2 f0 = __half22float2(h0);
    float2 f1 = __half22float2(h1);
    return make_float4(f0.x, f0.y, f1.x, f1.y);
}

__global__ __launch_bounds__(256)
void conv_silu_kernel(const float* __restrict__ conv_w) {
    const int idx = blockIdx.x * blockDim.x + threadIdx.x;
    const int ig  = idx & (I_DIM / 4 - 1);
    const int mg  = idx >> 9;
    const int m0  = mg * 4;
    const int s0  = m0 & (SEQ - 1);
    const int i   = ig * 4;

    const float4 w0 = ((const float4*)conv_w)[i + 0];
    const float4 w1 = ((const float4*)conv_w)[i + 1];
    const float4 w2 = ((const float4*)conv_w)[i + 2];
    const float4 w3 = ((const float4*)conv_w)[i + 3];

    float4 r[7];
#pragma unroll
    for (int t = 0; t < 7; t++) {
        int sp = s0 - 3 + t;
        if (sp >= 0)
            r[t] = ld4h(g_xzh + (size_t)(m0 - 3 + t) * I2_DIM + i);
        else
            r[t] = make_float4(0.f, 0.f, 0.f, 0.f);
    }

#pragma unroll
    for (int o = 0; o < 4; o++) {
        float4 acc;
        acc.x = r[o].x * w0.x + r[o+1].x * w0.y + r[o+2].x * w0.z + r[o+3].x * w0.w;
        acc.y = r[o].y * w1.x + r[o+1].y * w1.y + r[o+2].y * w1.z + r[o+3].y * w1.w;
        acc.z = r[o].z * w2.x + r[o+1].z * w2.y + r[o+2].z * w2.z + r[o+3].z * w2.w;
        acc.w = r[o].w * w3.x + r[o+1].w * w3.y + r[o+2].w * w3.z + r[o+3].w * w3.w;
        acc.x = acc.x / (1.f + __expf(-acc.x));
        acc.y = acc.y / (1.f + __expf(-acc.y));
        acc.z = acc.z / (1.f + __expf(-acc.z));
        acc.w = acc.w / (1.f + __expf(-acc.w));
        uint2 st;
        st.x = h2_u32(__floats2half2_rn(acc.x, acc.y));
        st.y = h2_u32(__floats2half2_rn(acc.z, acc.w));
        *(uint2*)(g_xch + (size_t)(m0 + o) * I_DIM + i) = st;
    }
}

// ---------------------------------------------------------------------------
// Middle stage 2: xproj. 2 rows/warp, 256 thr, 16 rows/block, W_x chunk 256
// staged in smem. Reads fp16 xc. (R15 config — measured 34.5 us.)
// ---------------------------------------------------------------------------
#define PROJ_ROWS 16
#define PROJ_KC   256
#define PROJ_SMEM (P_DIM * PROJ_KC * 4)   // 33792 B

__global__ __launch_bounds__(256)
void proj_kernel(const float* __restrict__ W_x) {
    extern __shared__ float wxs[];
    const int tid  = threadIdx.x;
    const int lane = tid & 31;
    const int wid  = tid >> 5;
    const int r0   = blockIdx.x * PROJ_ROWS + wid * 2;

    const __half* xp0 = g_xch + (size_t)(r0 + 0) * I_DIM;
    const __half* xp1 = g_xch + (size_t)(r0 + 1) * I_DIM;

    float acc0[P_DIM], acc1[P_DIM];
#pragma unroll
    for (int p = 0; p < P_DIM; p++) { acc0[p] = 0.f; acc1[p] = 0.f; }

    for (int k0 = 0; k0 < I_DIM; k0 += PROJ_KC) {
        __syncthreads();
        for (int f = tid; f < P_DIM * (PROJ_KC / 4); f += 256) {
            int p  = f / (PROJ_KC / 4);
            int kq = f % (PROJ_KC / 4);
            ((float4*)wxs)[f] = ((const float4*)(W_x + (size_t)p * I_DIM + k0))[kq];
        }
        __syncthreads();

#pragma unroll
        for (int it = 0; it < PROJ_KC / 128; it++) {
            const int kf = it * 32 + lane;
            float4 x0 = ld4h(xp0 + k0 + kf * 4);
            float4 x1 = ld4h(xp1 + k0 + kf * 4);
#pragma unroll
            for (int p = 0; p < P_DIM; p++) {
                float4 w = ((const float4*)wxs)[p * (PROJ_KC / 4) + kf];
                acc0[p] = fmaf(x0.x, w.x, fmaf(x0.y, w.y, fmaf(x0.z, w.z, fmaf(x0.w, w.w, acc0[p]))));
                acc1[p] = fmaf(x1.x, w.x, fmaf(x1.y, w.y, fmaf(x1.z, w.z, fmaf(x1.w, w.w, acc1[p]))));
            }
        }
    }

#pragma unroll
    for (int p = 0; p < P_DIM; p++) {
        float v0 = acc0[p], v1 = acc1[p];
#pragma unroll
        for (int off = 16; off > 0; off >>= 1) {
            v0 += __shfl_down_sync(0xffffffffu, v0, off);
            v1 += __shfl_down_sync(0xffffffffu, v1, off);
        }
        if (lane == 0) {
            g_proj[(size_t)(r0 + 0) * P_DIM + p] = v0;
            g_proj[(size_t)(r0 + 1) * P_DIM + p] = v1;
        }
    }
}

// ---------------------------------------------------------------------------
// Middle stage 3: ssm + gate. 148 blocks, 27/28 rows each (balanced fill).
// ---------------------------------------------------------------------------
#define SSM_MAXR 28

__global__ __launch_bounds__(256)
void ssm_kernel(const float* __restrict__ D) {
    const int bid  = blockIdx.x;
    const int rows = 27 + (bid < 100 ? 1 : 0);
    const int rb   = bid * 27 + (bid < 100 ? bid : 100);
    const int tid  = threadIdx.x;

    __shared__ float delta_s[SSM_MAXR];
    __shared__ float bc_s[SSM_MAXR][N_DIM];

    if (tid < rows) {
        const float* pr = g_proj + (size_t)(rb + tid) * P_DIM;
        float v = pr[0];
        delta_s[tid] = (v > 20.f) ? v : log1pf(__expf(v));
#pragma unroll
        for (int n = 0; n < N_DIM; n++)
            bc_s[tid][n] = pr[1 + n] * pr[1 + N_DIM + n];
    }
    __syncthreads();

    for (int ii = tid; ii < I_DIM; ii += 256) {
        float a[N_DIM];
        *(float4*)&a[0]  = *(const float4*)(g_Aneg + ii * N_DIM + 0);
        *(float4*)&a[4]  = *(const float4*)(g_Aneg + ii * N_DIM + 4);
        *(float4*)&a[8]  = *(const float4*)(g_Aneg + ii * N_DIM + 8);
        *(float4*)&a[12] = *(const float4*)(g_Aneg + ii * N_DIM + 12);
        const float d = D[ii];

#pragma unroll 4
        for (int mm = 0; mm < rows; mm++) {
            const int m = rb + mm;
            const float delta = delta_s[mm];
            float acc = d;
#pragma unroll
            for (int n = 0; n < N_DIM; n++)
                acc = fmaf(bc_s[mm][n], __expf(delta * a[n]), acc);
            float xcv = __half2float(g_xch[(size_t)m * I_DIM + ii]);
            float zv  = __half2float(g_xzh[(size_t)m * I2_DIM + I_DIM + ii]);
            float gz  = zv / (1.f + __expf(-zv));
            g_yzh[(size_t)m * I_DIM + ii] = __float2half_rn(xcv * acc * gz);
        }
    }
}

// ---------------------------------------------------------------------------
// Launcher
// ---------------------------------------------------------------------------
extern "C" void kernel_launch(void* const* d_in, const int* in_sizes, int n_in,
                              void* d_out, int out_size) {
    const float* x      = (const float*)d_in[0];
    const float* W_in   = (const float*)d_in[1];
    const float* conv_w = (const float*)d_in[2];
    const float* W_x    = (const float*)d_in[3];
    const float* A_log  = (const float*)d_in[4];
    const float* D      = (const float*)d_in[5];
    const float* W_out  = (const float*)d_in[6];
    float* out = (float*)d_out;

    __half *xzh_ptr, *yzh_ptr, *xrh_ptr, *wirh_ptr, *worh_ptr;
    cudaGetSymbolAddress((void**)&xzh_ptr,  g_xzh);
    cudaGetSymbolAddress((void**)&yzh_ptr,  g_yzh);
    cudaGetSymbolAddress((void**)&xrh_ptr,  g_xrh);
    cudaGetSymbolAddress((void**)&wirh_ptr, g_wirh);
    cudaGetSymbolAddress((void**)&worh_ptr, g_worh);

    cudaFuncSetAttribute(gemm_f16_mma<__half>,
                         cudaFuncAttributeMaxDynamicSharedMemorySize, GEMM_SMEM_BYTES);
    cudaFuncSetAttribute(gemm_f16_mma<float>,
                         cudaFuncAttributeMaxDynamicSharedMemorySize, GEMM_SMEM_BYTES);
    cudaFuncSetAttribute(proj_kernel,
                         cudaFuncAttributeMaxDynamicSharedMemorySize, PROJ_SMEM);

    // 0) fused prep: fp16 conversions + A = -exp(A_log)
    prep_kernel<<<(N8_TOT + 255) / 256, 256>>>(x, W_in, W_out, A_log);

    // 1) xz = x @ W_in^T : 1024 tiles over persistent 296-CTA grid (fp16 out)
    gemm_f16_mma<__half><<<GEMM_GRID, 128, GEMM_SMEM_BYTES>>>(xrh_ptr, wirh_ptr, xzh_ptr,
                                                              M_DIM, I2_DIM, H_DIM);

    // 2) middle
    conv_silu_kernel<<<(M_DIM / 4) * (I_DIM / 4) / 256, 256>>>(conv_w);
    proj_kernel<<<M_DIM / PROJ_ROWS, 256, PROJ_SMEM>>>(W_x);
    ssm_kernel<<<148, 256>>>(D);

    // 3) out = yz @ W_out^T : 256 tiles over persistent grid (fp32 out)
    gemm_f16_mma<float><<<GEMM_GRID, 128, GEMM_SMEM_BYTES>>>(yzh_ptr, worh_ptr, out,
                                                             M_DIM, H_DIM, I_DIM);
}